// round 2
// baseline (speedup 1.0000x reference)
#include <cuda_runtime.h>

#define N   1024
#define T   256          // threads per block
#define CPT 4            // columns per thread (T*CPT == N)

// Order-preserving float -> uint32 mapping (exact, bijective, monotone).
__device__ __forceinline__ unsigned fkey(float f) {
    unsigned k = __float_as_uint(f);
    return (k & 0x80000000u) ? ~k : (k | 0x80000000u);
}
__device__ __forceinline__ float funkey(unsigned k) {
    unsigned b = (k & 0x80000000u) ? (k & 0x7fffffffu) : ~k;
    return __uint_as_float(b);
}

// Exact Jonker-Volgenant LAP, one persistent block, 4 columns per thread.
// Cost C(i,j) = ||a_i - b_j|| recomputed on the fly (a-row broadcast from
// shared as float4 {ax,ay,az,u}, b columns in registers).
__global__ __launch_bounds__(T, 1)
void emd_jv_kernel(const float* __restrict__ gt,
                   const float* __restrict__ gen,
                   float* __restrict__ out) {
    __shared__ float4 s_row[N];                 // {ax, ay, az, u}
    __shared__ int    s_p[N];                   // p[j] = row matched to col j (-1 free)
    __shared__ unsigned short s_way[N];         // predecessor column on alt path
    __shared__ unsigned long long s_best[2];    // double-buffered (key<<32 | j)
    __shared__ int    s_i0;                     // row to relax from; -1 => augment
    __shared__ float  s_sum[T / 32];

    const int tid  = threadIdx.x;
    const int lane = tid & 31;
    const int wid  = tid >> 5;
    const int jb   = tid * CPT;                 // first column owned by this thread

    // ---- init ----
    #pragma unroll
    for (int k = 0; k < CPT; ++k) {
        const int r = jb + k;
        s_row[r] = make_float4(gt[3 * r], gt[3 * r + 1], gt[3 * r + 2], 0.0f);
        s_p[r] = -1;
    }
    // b columns: 12 consecutive floats -> 3 x float4
    const float4* g4 = (const float4*)gen;
    const float4 f0 = g4[3 * tid], f1 = g4[3 * tid + 1], f2 = g4[3 * tid + 2];
    const float bx[CPT] = {f0.x, f0.w, f1.z, f2.y};
    const float by[CPT] = {f0.y, f1.x, f1.w, f2.z};
    const float bz[CPT] = {f0.z, f1.y, f2.x, f2.w};

    float v[CPT] = {0.0f, 0.0f, 0.0f, 0.0f};    // column potentials
    if (tid == 0) { s_best[0] = ~0ull; s_best[1] = ~0ull; }

    int par = 0;

    for (int i = 0; i < N; ++i) {
        float minv[CPT] = {3.0e38f, 3.0e38f, 3.0e38f, 3.0e38f};
        int   pown[CPT];                        // matched row of my used columns
        unsigned usedm = 0;
        int   j0 = N;                           // virtual column
        float dsum = 0.0f;                      // accumulates u[i] (thread 0)
        int   j1 = -1;

        if (tid == 0) s_i0 = i;
        __syncthreads();                        // covers prev augment + s_i0

        while (true) {
            // ---- relax free columns from row i0 ----
            const int i0 = s_i0;
            const float4 row = s_row[i0];       // one LDS.128 broadcast
            unsigned key = 0xffffffffu;
            int kb = 0;
            #pragma unroll
            for (int k = 0; k < CPT; ++k) {
                if (!((usedm >> k) & 1u)) {
                    const float dx = row.x - bx[k], dy = row.y - by[k], dz = row.z - bz[k];
                    const float d2 = fmaf(dx, dx, fmaf(dy, dy, dz * dz));
                    const float c  = d2 * rsqrtf(fmaxf(d2, 1e-30f));
                    const float cur = c - row.w - v[k];
                    if (cur < minv[k]) { minv[k] = cur; s_way[jb + k] = (unsigned short)j0; }
                    const unsigned kk = fkey(minv[k]);
                    if (kk < key) { key = kk; kb = k; }
                }
            }

            // ---- fused exact argmin (one barrier) ----
            const unsigned wmin = __reduce_min_sync(0xffffffffu, key);
            const unsigned bal  = __ballot_sync(0xffffffffu, key == wmin);
            if (wmin != 0xffffffffu && lane == __ffs(bal) - 1)
                atomicMin(&s_best[par],
                          ((unsigned long long)wmin << 32) | (unsigned)(jb + kb));
            if (tid == 0) s_best[par ^ 1] = ~0ull;   // reset other slot
            __syncthreads();                          // B1

            const unsigned long long best = s_best[par];
            const float delta = funkey((unsigned)(best >> 32));
            j1 = (int)(best & 0xffffffffu);

            // ---- dual updates ----
            #pragma unroll
            for (int k = 0; k < CPT; ++k) {
                if ((usedm >> k) & 1u) {
                    v[k] -= delta;
                    s_row[pown[k]].w += delta;   // distinct rows: no conflict
                } else {
                    minv[k] -= delta;
                }
            }
            dsum += delta;

            // ---- settle j1; owner publishes its matched row ----
            if ((j1 >> 2) == tid) {
                const int k1 = j1 & 3;
                const int pj = s_p[j1];
                usedm |= 1u << k1;
                pown[k1] = pj;
                s_i0 = pj;                        // -1 => augment
            }
            par ^= 1;
            __syncthreads();                      // B2

            if (s_i0 < 0) break;
            j0 = j1;
        }

        // ---- augment alternating path (thread 0) ----
        if (tid == 0) {
            s_row[i].w = dsum;                    // persist u[i]
            int jj = j1;
            while (true) {
                const int jw = s_way[jj];
                if (jw == N) { s_p[jj] = i; break; }
                s_p[jj] = s_p[jw];
                jj = jw;
            }
        }
    }
    __syncthreads();

    // ---- mean of matched distances (exact sqrt) ----
    float acc = 0.0f;
    #pragma unroll
    for (int k = 0; k < CPT; ++k) {
        const int pi = s_p[jb + k];
        const float4 row = s_row[pi];
        const float dx = row.x - bx[k], dy = row.y - by[k], dz = row.z - bz[k];
        acc += sqrtf(fmaf(dx, dx, fmaf(dy, dy, dz * dz)));
    }
    #pragma unroll
    for (int o = 16; o; o >>= 1) acc += __shfl_down_sync(0xffffffffu, acc, o);
    if (lane == 0) s_sum[wid] = acc;
    __syncthreads();
    if (tid == 0) {
        float s = 0.0f;
        #pragma unroll
        for (int w = 0; w < T / 32; ++w) s += s_sum[w];
        out[0] = s * (1.0f / (float)N);
    }
}

extern "C" void kernel_launch(void* const* d_in, const int* in_sizes, int n_in,
                              void* d_out, int out_size) {
    const float* gt  = (const float*)d_in[0];   // (1,1024,3) fp32
    const float* gen = (const float*)d_in[1];   // (1,1024,3) fp32
    (void)in_sizes; (void)n_in; (void)out_size;
    emd_jv_kernel<<<1, T>>>(gt, gen, (float*)d_out);
}

// round 3
// speedup vs baseline: 1.4677x; 1.4677x over previous
#include <cuda_runtime.h>

#define N 1024

// Order-preserving float -> uint32 mapping (exact, bijective, monotone).
__device__ __forceinline__ unsigned fkey(float f) {
    unsigned k = __float_as_uint(f);
    return (k & 0x80000000u) ? ~k : (k | 0x80000000u);
}
__device__ __forceinline__ float funkey(unsigned k) {
    unsigned b = (k & 0x80000000u) ? (k & 0x7fffffffu) : ~k;
    return __uint_as_float(b);
}

// Exact LAPJV: column-reduction warm start + shortest augmenting paths.
// One persistent block, one thread per column. C(i,j) = ||a_i - b_j||
// recomputed on the fly (a-row broadcast from shared float4 {x,y,z,u},
// b column in registers). Optimal assignment => same cost as reference.
__global__ __launch_bounds__(1024, 1)
void emd_jv_kernel(const float* __restrict__ gt,
                   const float* __restrict__ gen,
                   float* __restrict__ out) {
    __shared__ float4 s_row[N];                 // {ax, ay, az, u}
    __shared__ int    s_p[N];                   // p[j] = row matched to col j (-1 free)
    __shared__ int    s_claim[N];               // col-reduction row claims
    __shared__ unsigned short s_way[N];         // predecessor column on alt path
    __shared__ unsigned long long s_best[2];    // double-buffered (key<<32 | j)
    __shared__ int    s_i0;                     // row to relax from; -1 => augment
    __shared__ float  s_sum[32];

    const int j    = threadIdx.x;
    const int lane = j & 31;
    const int wid  = j >> 5;

    // ---- load points ----
    s_row[j] = make_float4(gt[3 * j], gt[3 * j + 1], gt[3 * j + 2], 0.0f);
    s_p[j]     = -1;
    s_claim[j] = 0x7fffffff;
    const float bx = gen[3 * j], by = gen[3 * j + 1], bz = gen[3 * j + 2];
    if (j == 0) { s_best[0] = ~0ull; s_best[1] = ~0ull; }
    __syncthreads();

    // ---- phase 1: column reduction (v[j] = min_i C(i,j), claim argmin rows) ----
    float v = 3.0e38f;
    int   bi = 0;
    for (int i = 0; i < N; ++i) {
        const float4 row = s_row[i];            // broadcast
        const float dx = row.x - bx, dy = row.y - by, dz = row.z - bz;
        const float d2 = fmaf(dx, dx, fmaf(dy, dy, dz * dz));
        const float c  = d2 * rsqrtf(fmaxf(d2, 1e-30f));
        if (c < v) { v = c; bi = i; }           // ties -> lowest i (deterministic)
    }
    atomicMin(&s_claim[bi], j);                 // row claimed by lowest column
    __syncthreads();
    if (s_claim[bi] == j) s_p[j] = bi;          // matched at zero reduced cost
    __syncthreads();

    int par = 0;

    // ---- phase 2: shortest augmenting path for each free row ----
    for (int i = 0; i < N; ++i) {
        if (s_claim[i] != 0x7fffffff) continue; // row pre-matched

        float minv = 3.0e38f;
        bool  used = false;
        int   pown = 0;
        int   j0   = N;                         // virtual column
        float dsum = 0.0f;
        int   j1   = -1;

        if (j == 0) s_i0 = i;
        __syncthreads();                        // covers prev augment + s_i0

        while (true) {
            // ---- relax free columns from row i0 ----
            const int i0 = s_i0;
            unsigned key = 0xffffffffu;
            if (!used) {
                const float4 row = s_row[i0];   // one LDS.128 broadcast
                const float dx = row.x - bx, dy = row.y - by, dz = row.z - bz;
                const float d2 = fmaf(dx, dx, fmaf(dy, dy, dz * dz));
                const float c  = d2 * rsqrtf(fmaxf(d2, 1e-30f));
                const float cur = c - row.w - v;
                if (cur < minv) { minv = cur; s_way[j] = (unsigned short)j0; }
                key = fkey(minv);
            }

            // ---- fused exact argmin (one barrier) ----
            const unsigned wmin = __reduce_min_sync(0xffffffffu, key);
            const unsigned bal  = __ballot_sync(0xffffffffu, key == wmin);
            if (wmin != 0xffffffffu && lane == (__ffs(bal) - 1))
                atomicMin(&s_best[par],
                          ((unsigned long long)wmin << 32) | (unsigned)j);
            if (j == 0) s_best[par ^ 1] = ~0ull;     // reset other slot
            __syncthreads();                          // B1

            const unsigned long long best = s_best[par];
            const float delta = funkey((unsigned)(best >> 32));
            j1 = (int)(best & 0xffffffffu);

            // ---- dual updates ----
            if (used) { v -= delta; s_row[pown].w += delta; }
            else      { minv -= delta; }
            dsum += delta;

            // ---- settle j1; owner publishes its matched row ----
            if (j == j1) {
                const int pj = s_p[j];
                used = true; pown = pj;
                s_i0 = pj;                        // -1 => augment
            }
            par ^= 1;
            __syncthreads();                      // B2

            if (s_i0 < 0) break;
            j0 = j1;
        }

        // ---- augment alternating path (thread 0) ----
        if (j == 0) {
            s_row[i].w = dsum;                    // persist u[i]
            int jj = j1;
            while (true) {
                const int jw = s_way[jj];
                if (jw == N) { s_p[jj] = i; break; }
                s_p[jj] = s_p[jw];
                jj = jw;
            }
        }
    }
    __syncthreads();

    // ---- mean of matched distances (exact) ----
    const int pi = s_p[j];
    const float4 row = s_row[pi];
    const float dx = row.x - bx, dy = row.y - by, dz = row.z - bz;
    float acc = sqrtf(fmaf(dx, dx, fmaf(dy, dy, dz * dz)));
    #pragma unroll
    for (int o = 16; o; o >>= 1) acc += __shfl_down_sync(0xffffffffu, acc, o);
    if (lane == 0) s_sum[wid] = acc;
    __syncthreads();
    if (j == 0) {
        float s = 0.0f;
        #pragma unroll
        for (int w = 0; w < 32; ++w) s += s_sum[w];
        out[0] = s * (1.0f / (float)N);
    }
}

extern "C" void kernel_launch(void* const* d_in, const int* in_sizes, int n_in,
                              void* d_out, int out_size) {
    const float* gt  = (const float*)d_in[0];   // (1,1024,3) fp32
    const float* gen = (const float*)d_in[1];   // (1,1024,3) fp32
    (void)in_sizes; (void)n_in; (void)out_size;
    emd_jv_kernel<<<1, 1024>>>(gt, gen, (float*)d_out);
}

// round 4
// speedup vs baseline: 1.8293x; 1.2464x over previous
#include <cuda_runtime.h>

#define N 1024

// Order-preserving float -> uint32 mapping (exact, bijective, monotone).
__device__ __forceinline__ unsigned fkey(float f) {
    unsigned k = __float_as_uint(f);
    return (k & 0x80000000u) ? ~k : (k | 0x80000000u);
}
__device__ __forceinline__ float funkey(unsigned k) {
    unsigned b = (k & 0x80000000u) ? (k & 0x7fffffffu) : ~k;
    return __uint_as_float(b);
}

// Exact LAPJV: column-reduction warm start + shortest augmenting paths in
// original (unshifted) Dijkstra scale -> one barrier per inner iteration,
// dual updates applied once per search. One block, one thread per column.
__global__ __launch_bounds__(1024, 1)
void emd_jv_kernel(const float* __restrict__ gt,
                   const float* __restrict__ gen,
                   float* __restrict__ out) {
    __shared__ float4 s_row[N];                 // {ax, ay, az, u}
    __shared__ int    s_p[N];                   // p[j] = row matched to col j (-1 free)
    __shared__ int    s_claim[N];               // col-reduction row claims
    __shared__ unsigned short s_way[N];         // predecessor column on alt path
    __shared__ unsigned long long s_best[3];    // triple-buffered (key<<32 | j<<11 | p+1)
    __shared__ float  s_sum[32];

    const int j    = threadIdx.x;
    const int lane = j & 31;
    const int wid  = j >> 5;

    // ---- load points ----
    s_row[j] = make_float4(gt[3 * j], gt[3 * j + 1], gt[3 * j + 2], 0.0f);
    s_p[j]     = -1;
    s_claim[j] = 0x7fffffff;
    const float bx = gen[3 * j], by = gen[3 * j + 1], bz = gen[3 * j + 2];
    if (j < 3) s_best[j] = ~0ull;
    __syncthreads();

    // ---- phase 1: column reduction (v[j] = min_i C(i,j), claim argmin rows) ----
    float v = 3.0e38f;
    int   bi = 0;
    for (int i = 0; i < N; ++i) {
        const float4 row = s_row[i];
        const float dx = row.x - bx, dy = row.y - by, dz = row.z - bz;
        const float d2 = fmaf(dx, dx, fmaf(dy, dy, dz * dz));
        const float c  = d2 * rsqrtf(fmaxf(d2, 1e-30f));
        if (c < v) { v = c; bi = i; }
    }
    atomicMin(&s_claim[bi], j);
    __syncthreads();
    if (s_claim[bi] == j) s_p[j] = bi;          // matched at zero reduced cost
    __syncthreads();

    int par = 0;

    // ---- phase 2: shortest augmenting path for each free row ----
    for (int i = 0; i < N; ++i) {
        if (s_claim[i] != 0x7fffffff) continue; // row pre-matched (uniform branch)
        __syncthreads();                        // prev augment + dual writes visible

        float M   = 3.0e38f;                    // Dijkstra label (original scale)
        float D   = 0.0f;                       // settled distance of current source
        int   i0  = i;                          // relax source row
        int   j0  = N;                          // previously settled column (virtual)
        const int pj = s_p[j];                  // register copy, stable in-search
        bool  used = false;
        float Dj = 0.0f;                        // my label at settle
        int   pown = 0;                         // my matched row at settle
        int   j1f; float Dfinal;

        while (true) {
            // ---- relax free columns from (i0, D) ----
            unsigned key = 0xffffffffu;
            if (!used) {
                const float4 row = s_row[i0];   // LDS.128 broadcast
                const float dx = row.x - bx, dy = row.y - by, dz = row.z - bz;
                const float d2 = fmaf(dx, dx, fmaf(dy, dy, dz * dz));
                const float c  = d2 * rsqrtf(fmaxf(d2, 1e-30f));
                const float cur = (c - row.w - v) + D;
                if (cur < M) { M = cur; s_way[j] = (unsigned short)j0; }
                key = fkey(M);
            }

            // ---- exact argmin: warp REDUX + single shared atomicMin ----
            const unsigned wmin = __reduce_min_sync(0xffffffffu, key);
            const unsigned bal  = __ballot_sync(0xffffffffu, key == wmin);
            if (wmin != 0xffffffffu && lane == (__ffs(bal) - 1))
                atomicMin(&s_best[par],
                          ((unsigned long long)wmin << 32)
                          | ((unsigned)j << 11) | (unsigned)(pj + 1));
            if (j == 0) s_best[par + 1 == 3 ? 0 : par + 1] = ~0ull;
            __syncthreads();                    // the one barrier

            const unsigned long long best = s_best[par];
            par = (par + 1 == 3) ? 0 : par + 1;
            const float Dn  = funkey((unsigned)(best >> 32));
            const int   j1  = (int)((best >> 11) & 0x3ffu);
            const int   i0n = (int)(best & 0x7ffu) - 1;

            if (j == j1 && i0n >= 0) { used = true; Dj = Dn; pown = i0n; }
            if (i0n < 0) { j1f = j1; Dfinal = Dn; break; }
            i0 = i0n; D = Dn; j0 = j1;
        }

        // ---- post-search dual updates (once, not per-iteration) ----
        if (used) { v += Dj - Dfinal; s_row[pown].w += Dfinal - Dj; }
        if (j == 0) {
            s_row[i].w += Dfinal;               // u of the newly assigned row
            int jj = j1f;                       // augment alternating path
            while (true) {
                const int jw = s_way[jj];
                if (jw == N) { s_p[jj] = i; break; }
                s_p[jj] = s_p[jw];
                jj = jw;
            }
        }
    }
    __syncthreads();

    // ---- mean of matched distances (exact sqrt) ----
    const int pi = s_p[j];
    const float4 row = s_row[pi];
    const float dx = row.x - bx, dy = row.y - by, dz = row.z - bz;
    float acc = sqrtf(fmaf(dx, dx, fmaf(dy, dy, dz * dz)));
    #pragma unroll
    for (int o = 16; o; o >>= 1) acc += __shfl_down_sync(0xffffffffu, acc, o);
    if (lane == 0) s_sum[wid] = acc;
    __syncthreads();
    if (j == 0) {
        float s = 0.0f;
        #pragma unroll
        for (int w = 0; w < 32; ++w) s += s_sum[w];
        out[0] = s * (1.0f / (float)N);
    }
}

extern "C" void kernel_launch(void* const* d_in, const int* in_sizes, int n_in,
                              void* d_out, int out_size) {
    const float* gt  = (const float*)d_in[0];   // (1,1024,3) fp32
    const float* gen = (const float*)d_in[1];   // (1,1024,3) fp32
    (void)in_sizes; (void)n_in; (void)out_size;
    emd_jv_kernel<<<1, 1024>>>(gt, gen, (float*)d_out);
}